// round 1
// baseline (speedup 1.0000x reference)
#include <cuda_runtime.h>
#include <math.h>

// Problem constants
#define B    64
#define T    2048
#define ENC  512
#define DEC  512
#define ATTN 256
#define TT   16           // t-rows per energy block

// ---- scratch (no allocations allowed) ----
__device__ float g_proj_dec[B * ATTN];
__device__ float g_energy[B * T];
__device__ int   g_mask_is_byte;

// ---------------------------------------------------------------------------
// Detect whether mask buffer is 1-byte bools or int32 0/1.
// If int32 little-endian 0/1, every byte at index % 4 != 0 is zero.
// If byte bools (~50% ones over 131072 entries), some of those bytes are 1.
// ---------------------------------------------------------------------------
__global__ void detect_mask_kernel(const unsigned char* __restrict__ m) {
    __shared__ int f;
    if (threadIdx.x == 0) f = 0;
    __syncthreads();
    int local = 0;
    for (int i = threadIdx.x; i < B * T; i += blockDim.x)
        if ((i & 3) && m[i]) local = 1;
    if (local) atomicOr(&f, 1);
    __syncthreads();
    if (threadIdx.x == 0) g_mask_is_byte = f;
}

// ---------------------------------------------------------------------------
// proj_dec[b,a] = sum_d dec_hidden[b,d] * W_dec[d,a]
// grid = B, block = 256 (one thread per a)
// ---------------------------------------------------------------------------
__global__ void projdec_kernel(const float* __restrict__ dec,
                               const float* __restrict__ Wd) {
    __shared__ float sd[DEC];
    const int b = blockIdx.x, tid = threadIdx.x;
    sd[tid]       = dec[b * DEC + tid];
    sd[tid + 256] = dec[b * DEC + tid + 256];
    __syncthreads();
    float acc = 0.f;
    #pragma unroll 8
    for (int k = 0; k < DEC; k++)
        acc = fmaf(sd[k], Wd[k * ATTN + tid], acc);
    g_proj_dec[b * ATTN + tid] = acc;
}

// ---------------------------------------------------------------------------
// energy[b,t] = sum_a tanh( (enc[b,t,:] @ W_enc)[a] + proj_dec[b,a] ) * v[a]
// grid = (T/TT, B), block = 256. Thread owns column a = tid, TT accumulators.
// enc tile in smem (float4 broadcast), W_enc streamed from L2.
// ---------------------------------------------------------------------------
__global__ __launch_bounds__(256)
void energy_kernel(const float* __restrict__ enc,
                   const float* __restrict__ We,
                   const float* __restrict__ v) {
    __shared__ float4 se[TT][ENC / 4];   // 16 x 512 floats = 32 KB

    const int b   = blockIdx.y;
    const int t0  = blockIdx.x * TT;
    const int tid = threadIdx.x;

    // cooperative load of enc tile as float4 (fully coalesced)
    const float4* encv =
        (const float4*)(enc + ((size_t)b * T + t0) * ENC);
    for (int i = tid; i < TT * (ENC / 4); i += 256) {
        int r = i >> 7, c = i & 127;
        se[r][c] = encv[(size_t)r * (ENC / 4) + c];
    }
    __syncthreads();

    float acc[TT];
    #pragma unroll
    for (int t = 0; t < TT; t++) acc[t] = 0.f;

    const float* Wcol = We + tid;   // column a = tid, row stride ATTN
    #pragma unroll 2
    for (int k4 = 0; k4 < ENC / 4; k4++) {
        const float w0 = Wcol[(k4 * 4 + 0) * ATTN];
        const float w1 = Wcol[(k4 * 4 + 1) * ATTN];
        const float w2 = Wcol[(k4 * 4 + 2) * ATTN];
        const float w3 = Wcol[(k4 * 4 + 3) * ATTN];
        #pragma unroll
        for (int t = 0; t < TT; t++) {
            const float4 e4 = se[t][k4];       // smem broadcast
            acc[t] = fmaf(e4.x, w0, acc[t]);
            acc[t] = fmaf(e4.y, w1, acc[t]);
            acc[t] = fmaf(e4.z, w2, acc[t]);
            acc[t] = fmaf(e4.w, w3, acc[t]);
        }
    }

    const float vv = v[tid];
    const float pd = g_proj_dec[b * ATTN + tid];

    __syncthreads();                     // done reading se as enc tile
    float* rb = (float*)se;              // reuse smem for reduction
    #pragma unroll
    for (int t = 0; t < TT; t++)
        rb[t * 256 + tid] = tanhf(acc[t] + pd) * vv;
    __syncthreads();

    for (int s = 128; s > 0; s >>= 1) {
        if (tid < s) {
            #pragma unroll
            for (int t = 0; t < TT; t++)
                rb[t * 256 + tid] += rb[t * 256 + tid + s];
        }
        __syncthreads();
    }
    if (tid < TT)
        g_energy[b * T + t0 + tid] = rb[tid * 256];
}

// ---------------------------------------------------------------------------
// masked softmax over T; writes attn_w into d_out[B*ENC ...]
// grid = B, block = 256 (8 elements / thread)
// ---------------------------------------------------------------------------
__global__ void softmax_kernel(const void* __restrict__ mask,
                               float* __restrict__ attn_out) {
    const int b = blockIdx.x, tid = threadIdx.x;
    const bool isbyte = (g_mask_is_byte != 0);
    const unsigned char* mb = (const unsigned char*)mask;
    const int*           mi = (const int*)mask;

    float e[8];
    #pragma unroll
    for (int j = 0; j < 8; j++) {
        const int t = tid + j * 256;
        const int i = b * T + t;
        const bool m = isbyte ? (mb[i] != 0) : (mi[i] != 0);
        e[j] = m ? -INFINITY : g_energy[i];
    }

    __shared__ float sred[32];
    // --- block max ---
    float mx = e[0];
    #pragma unroll
    for (int j = 1; j < 8; j++) mx = fmaxf(mx, e[j]);
    #pragma unroll
    for (int o = 16; o > 0; o >>= 1)
        mx = fmaxf(mx, __shfl_xor_sync(0xffffffffu, mx, o));
    if ((tid & 31) == 0) sred[tid >> 5] = mx;
    __syncthreads();
    if (tid < 32) {
        float v2 = (tid < 8) ? sred[tid] : -INFINITY;
        #pragma unroll
        for (int o = 4; o > 0; o >>= 1)
            v2 = fmaxf(v2, __shfl_xor_sync(0xffffffffu, v2, o));
        if (tid == 0) sred[0] = v2;
    }
    __syncthreads();
    mx = sred[0];
    __syncthreads();

    const bool allmasked = !(mx > -INFINITY);

    // --- exp and block sum ---
    float ex[8];
    float s = 0.f;
    #pragma unroll
    for (int j = 0; j < 8; j++) {
        ex[j] = (allmasked || e[j] == -INFINITY) ? 0.f : expf(e[j] - mx);
        s += ex[j];
    }
    #pragma unroll
    for (int o = 16; o > 0; o >>= 1)
        s += __shfl_xor_sync(0xffffffffu, s, o);
    if ((tid & 31) == 0) sred[tid >> 5] = s;
    __syncthreads();
    if (tid < 32) {
        float v2 = (tid < 8) ? sred[tid] : 0.f;
        #pragma unroll
        for (int o = 4; o > 0; o >>= 1)
            v2 += __shfl_xor_sync(0xffffffffu, v2, o);
        if (tid == 0) sred[0] = v2;
    }
    __syncthreads();
    s = sred[0];

    const float inv = (s > 0.f) ? (1.f / s) : 0.f;
    #pragma unroll
    for (int j = 0; j < 8; j++) {
        const int t = tid + j * 256;
        attn_out[b * T + t] = ex[j] * inv;
    }
}

// ---------------------------------------------------------------------------
// context[b,e] = sum_t attn_w[b,t] * enc[b,t,e]
// grid = (ENC/128, B), block = 128 (thread owns one e-column)
// ---------------------------------------------------------------------------
__global__ void context_kernel(const float* __restrict__ enc,
                               const float* __restrict__ attn,
                               float* __restrict__ ctx) {
    __shared__ float sw[T];
    const int b = blockIdx.y;
    const int e = blockIdx.x * 128 + threadIdx.x;

    for (int i = threadIdx.x; i < T; i += 128)
        sw[i] = attn[b * T + i];
    __syncthreads();

    const float* ep = enc + (size_t)b * T * ENC + e;
    float a0 = 0.f, a1 = 0.f, a2 = 0.f, a3 = 0.f;
    for (int t = 0; t < T; t += 4) {
        a0 = fmaf(sw[t + 0], ep[(size_t)(t + 0) * ENC], a0);
        a1 = fmaf(sw[t + 1], ep[(size_t)(t + 1) * ENC], a1);
        a2 = fmaf(sw[t + 2], ep[(size_t)(t + 2) * ENC], a2);
        a3 = fmaf(sw[t + 3], ep[(size_t)(t + 3) * ENC], a3);
    }
    ctx[b * ENC + e] = (a0 + a1) + (a2 + a3);
}

// ---------------------------------------------------------------------------
extern "C" void kernel_launch(void* const* d_in, const int* in_sizes, int n_in,
                              void* d_out, int out_size) {
    const float* enc  = (const float*)d_in[0];   // [B,T,ENC]
    const float* dec  = (const float*)d_in[1];   // [B,DEC]
    const void*  mask = d_in[2];                 // [B,T] bool (byte or i32)
    const float* We   = (const float*)d_in[3];   // [ENC,ATTN]
    const float* Wd   = (const float*)d_in[4];   // [DEC,ATTN]
    const float* v    = (const float*)d_in[5];   // [ATTN]

    float* out_ctx  = (float*)d_out;             // [B,ENC]
    float* out_attn = out_ctx + B * ENC;         // [B,T]

    detect_mask_kernel<<<1, 256>>>((const unsigned char*)mask);
    projdec_kernel<<<B, 256>>>(dec, Wd);
    energy_kernel<<<dim3(T / TT, B), 256>>>(enc, We, v);
    softmax_kernel<<<B, 256>>>(mask, out_attn);
    context_kernel<<<dim3(ENC / 128, B), 128>>>(enc, out_attn, out_ctx);
}

// round 3
// speedup vs baseline: 1.9417x; 1.9417x over previous
#include <cuda_runtime.h>
#include <math.h>
#include <stdint.h>
#include <mma.h>

using namespace nvcuda;

// Problem constants
#define B    64
#define T    2048
#define ENC  512
#define DEC  512
#define ATTN 256

// Energy GEMM tiling
#define TILE_M  128
#define KC      32                 // K per pipeline chunk
#define NCHUNK  (ENC / KC)         // 16
#define A_LD    40                 // 32 + 8 pad (floats)
#define B_LD    264                // 256 + 8 pad (floats)
#define C_LD    264
#define A_BYTES (TILE_M * A_LD * 4)        // 20480
#define B_BYTES (KC * B_LD * 4)            // 33792
#define STAGE_B (A_BYTES + B_BYTES)        // 54272
#define META_B  2048
#define DYN_SMEM (META_B + TILE_M * C_LD * 4)   // 2048 + 135168 = 137216 (> 2*STAGE_B + meta)

// ---- scratch (no allocations allowed) ----
__device__ float g_proj_dec[B * ATTN];
__device__ float g_energy[B * T];
__device__ int   g_mask_is_byte;

// ---------------------------------------------------------------------------
__device__ __forceinline__ uint32_t smem_u32(const void* p) {
    uint32_t a;
    asm("{ .reg .u64 t; cvta.to.shared.u64 t, %1; cvt.u32.u64 %0, t; }" : "=r"(a) : "l"(p));
    return a;
}
__device__ __forceinline__ float fast_tanh(float x) {
    float y; asm("tanh.approx.f32 %0, %1;" : "=f"(y) : "f"(x)); return y;
}
__device__ __forceinline__ void cp_async16(uint32_t s, const void* g) {
    asm volatile("cp.async.cg.shared.global [%0], [%1], 16;" :: "r"(s), "l"(g));
}
#define CP_COMMIT() asm volatile("cp.async.commit_group;" ::: "memory")
#define CP_WAIT1()  asm volatile("cp.async.wait_group 1;"  ::: "memory")
#define CP_WAIT0()  asm volatile("cp.async.wait_group 0;"  ::: "memory")

// ---------------------------------------------------------------------------
// mask dtype detection (byte bools vs int32 0/1)
// ---------------------------------------------------------------------------
__global__ void detect_mask_kernel(const unsigned char* __restrict__ m) {
    __shared__ int f;
    if (threadIdx.x == 0) f = 0;
    __syncthreads();
    int local = 0;
    for (int i = threadIdx.x; i < B * T; i += blockDim.x)
        if ((i & 3) && m[i]) local = 1;
    if (local) atomicOr(&f, 1);
    __syncthreads();
    if (threadIdx.x == 0) g_mask_is_byte = f;
}

// ---------------------------------------------------------------------------
// proj_dec[b,a] = dec[b,:] @ W_dec[:,a]
// ---------------------------------------------------------------------------
__global__ void projdec_kernel(const float* __restrict__ dec,
                               const float* __restrict__ Wd) {
    __shared__ float sd[DEC];
    const int b = blockIdx.x, tid = threadIdx.x;
    sd[tid]       = dec[b * DEC + tid];
    sd[tid + 256] = dec[b * DEC + tid + 256];
    __syncthreads();
    float acc = 0.f;
    #pragma unroll 8
    for (int k = 0; k < DEC; k++)
        acc = fmaf(sd[k], Wd[k * ATTN + tid], acc);
    g_proj_dec[b * ATTN + tid] = acc;
}

// ---------------------------------------------------------------------------
// Fused energy kernel: WMMA tf32 GEMM (128x256x512) + tanh/dot-v epilogue.
// grid (T/128, B), block 512 (16 warps, 4x4 warp grid, 32x64 warp tile).
// ---------------------------------------------------------------------------
__device__ __forceinline__ void load_chunk(const float* __restrict__ enc_tile,
                                           const float* __restrict__ We,
                                           int c, uint32_t a_s, uint32_t b_s,
                                           int tid) {
    const int koff = c * KC;
    // A: 128 rows x 32 floats = 1024 float4 -> 2 per thread
    #pragma unroll
    for (int it = 0; it < 2; it++) {
        int idx = it * 512 + tid;
        int row = idx >> 3, seg = idx & 7;          // 8 x float4 per row
        cp_async16(a_s + (uint32_t)(row * A_LD + seg * 4) * 4,
                   enc_tile + (size_t)row * ENC + koff + seg * 4);
    }
    // B: 32 rows x 256 floats = 2048 float4 -> 4 per thread
    #pragma unroll
    for (int it = 0; it < 4; it++) {
        int idx = it * 512 + tid;
        int row = idx >> 6, seg = idx & 63;         // 64 x float4 per row
        cp_async16(b_s + (uint32_t)(row * B_LD + seg * 4) * 4,
                   We + (size_t)(koff + row) * ATTN + seg * 4);
    }
}

__global__ void __launch_bounds__(512, 1)
energy_wmma_kernel(const float* __restrict__ enc,
                   const float* __restrict__ We,
                   const float* __restrict__ v) {
    extern __shared__ char dsm[];
    float* pd_s = (float*)dsm;                       // 256 f32
    float* v_s  = (float*)(dsm + ATTN * 4);          // 256 f32
    char*  pipe = dsm + META_B;                      // 2 stages
    float* c_s  = (float*)(dsm + META_B);            // epilogue reuse

    const uint32_t pipe_u = smem_u32(pipe);

    const int tid  = threadIdx.x;
    const int wid  = tid >> 5;
    const int wm   = wid & 3;          // 0..3  (M)
    const int wn   = wid >> 2;         // 0..3  (N)
    const int b    = blockIdx.y;
    const int t0   = blockIdx.x * TILE_M;
    const float* enc_tile = enc + ((size_t)b * T + t0) * ENC;

    if (tid < 256) {
        pd_s[tid] = g_proj_dec[b * ATTN + tid];
        v_s[tid]  = v[tid];
    }

    wmma::fragment<wmma::accumulator, 16, 16, 8, float> cf[2][4];
    #pragma unroll
    for (int i = 0; i < 2; i++)
        #pragma unroll
        for (int j = 0; j < 4; j++)
            wmma::fill_fragment(cf[i][j], 0.0f);

    // prologue: chunk 0 -> stage 0
    load_chunk(enc_tile, We, 0, pipe_u, pipe_u + A_BYTES, tid);
    CP_COMMIT();

    for (int c = 0; c < NCHUNK; c++) {
        const int sp = c & 1;
        if (c + 1 < NCHUNK) {
            const int sl = (c + 1) & 1;
            load_chunk(enc_tile, We, c + 1,
                       pipe_u + sl * STAGE_B, pipe_u + sl * STAGE_B + A_BYTES, tid);
            CP_COMMIT();
            CP_WAIT1();
        } else {
            CP_WAIT0();
        }
        __syncthreads();

        const float* a_s = (const float*)(pipe + sp * STAGE_B);
        const float* b_s = (const float*)(pipe + sp * STAGE_B + A_BYTES);

        #pragma unroll
        for (int ks = 0; ks < KC / 8; ks++) {
            wmma::fragment<wmma::matrix_a, 16, 16, 8, wmma::precision::tf32,
                           wmma::row_major> af[2];
            wmma::fragment<wmma::matrix_b, 16, 16, 8, wmma::precision::tf32,
                           wmma::row_major> bf[4];
            #pragma unroll
            for (int i = 0; i < 2; i++) {
                wmma::load_matrix_sync(af[i],
                    a_s + (size_t)(wm * 32 + i * 16) * A_LD + ks * 8, A_LD);
                #pragma unroll
                for (int e = 0; e < af[i].num_elements; e++)
                    af[i].x[e] = wmma::__float_to_tf32(af[i].x[e]);
            }
            #pragma unroll
            for (int j = 0; j < 4; j++) {
                wmma::load_matrix_sync(bf[j],
                    b_s + (size_t)(ks * 8) * B_LD + wn * 64 + j * 16, B_LD);
                #pragma unroll
                for (int e = 0; e < bf[j].num_elements; e++)
                    bf[j].x[e] = wmma::__float_to_tf32(bf[j].x[e]);
            }
            #pragma unroll
            for (int i = 0; i < 2; i++)
                #pragma unroll
                for (int j = 0; j < 4; j++)
                    wmma::mma_sync(cf[i][j], af[i], bf[j], cf[i][j]);
        }
        __syncthreads();
    }

    // store C tile (128 x 256, ld 264) and reduce
    #pragma unroll
    for (int i = 0; i < 2; i++)
        #pragma unroll
        for (int j = 0; j < 4; j++)
            wmma::store_matrix_sync(
                c_s + (size_t)(wm * 32 + i * 16) * C_LD + wn * 64 + j * 16,
                cf[i][j], C_LD, wmma::mem_row_major);
    __syncthreads();

    const int row = tid >> 2, q = tid & 3;
    const float* crow = c_s + (size_t)row * C_LD + q * 64;
    const float* pdq  = pd_s + q * 64;
    const float* vq   = v_s + q * 64;
    float e = 0.f;
    #pragma unroll 8
    for (int j = 0; j < 64; j++)
        e = fmaf(fast_tanh(crow[j] + pdq[j]), vq[j], e);
    e += __shfl_xor_sync(0xffffffffu, e, 1);
    e += __shfl_xor_sync(0xffffffffu, e, 2);
    if (q == 0)
        g_energy[b * T + t0 + row] = e;
}

// ---------------------------------------------------------------------------
// masked softmax over T
// ---------------------------------------------------------------------------
__global__ void softmax_kernel(const void* __restrict__ mask,
                               float* __restrict__ attn_out) {
    const int b = blockIdx.x, tid = threadIdx.x;
    const bool isbyte = (g_mask_is_byte != 0);
    const unsigned char* mb = (const unsigned char*)mask;
    const int*           mi = (const int*)mask;

    float e[8];
    #pragma unroll
    for (int j = 0; j < 8; j++) {
        const int i = b * T + tid + j * 256;
        const bool m = isbyte ? (mb[i] != 0) : (mi[i] != 0);
        e[j] = m ? -INFINITY : g_energy[i];
    }

    __shared__ float sred[32];
    float mx = e[0];
    #pragma unroll
    for (int j = 1; j < 8; j++) mx = fmaxf(mx, e[j]);
    #pragma unroll
    for (int o = 16; o > 0; o >>= 1)
        mx = fmaxf(mx, __shfl_xor_sync(0xffffffffu, mx, o));
    if ((tid & 31) == 0) sred[tid >> 5] = mx;
    __syncthreads();
    if (tid < 32) {
        float v2 = (tid < 8) ? sred[tid] : -INFINITY;
        #pragma unroll
        for (int o = 4; o > 0; o >>= 1)
            v2 = fmaxf(v2, __shfl_xor_sync(0xffffffffu, v2, o));
        if (tid == 0) sred[0] = v2;
    }
    __syncthreads();
    mx = sred[0];
    __syncthreads();

    const bool allmasked = !(mx > -INFINITY);

    float ex[8], s = 0.f;
    #pragma unroll
    for (int j = 0; j < 8; j++) {
        ex[j] = (allmasked || e[j] == -INFINITY) ? 0.f : expf(e[j] - mx);
        s += ex[j];
    }
    #pragma unroll
    for (int o = 16; o > 0; o >>= 1)
        s += __shfl_xor_sync(0xffffffffu, s, o);
    if ((tid & 31) == 0) sred[tid >> 5] = s;
    __syncthreads();
    if (tid < 32) {
        float v2 = (tid < 8) ? sred[tid] : 0.f;
        #pragma unroll
        for (int o = 4; o > 0; o >>= 1)
            v2 += __shfl_xor_sync(0xffffffffu, v2, o);
        if (tid == 0) sred[0] = v2;
    }
    __syncthreads();
    s = sred[0];

    const float inv = (s > 0.f) ? (1.f / s) : 0.f;
    #pragma unroll
    for (int j = 0; j < 8; j++)
        attn_out[b * T + tid + j * 256] = ex[j] * inv;
}

// ---------------------------------------------------------------------------
// context[b,e] = sum_t attn_w[b,t] * enc[b,t,e]
// ---------------------------------------------------------------------------
__global__ void context_kernel(const float* __restrict__ enc,
                               const float* __restrict__ attn,
                               float* __restrict__ ctx) {
    __shared__ float sw[T];
    const int b = blockIdx.y;
    const int e = blockIdx.x * 128 + threadIdx.x;

    for (int i = threadIdx.x; i < T; i += 128)
        sw[i] = attn[b * T + i];
    __syncthreads();

    const float* ep = enc + (size_t)b * T * ENC + e;
    float a0 = 0.f, a1 = 0.f, a2 = 0.f, a3 = 0.f;
    for (int t = 0; t < T; t += 4) {
        a0 = fmaf(sw[t + 0], ep[(size_t)(t + 0) * ENC], a0);
        a1 = fmaf(sw[t + 1], ep[(size_t)(t + 1) * ENC], a1);
        a2 = fmaf(sw[t + 2], ep[(size_t)(t + 2) * ENC], a2);
        a3 = fmaf(sw[t + 3], ep[(size_t)(t + 3) * ENC], a3);
    }
    ctx[b * ENC + e] = (a0 + a1) + (a2 + a3);
}

// ---------------------------------------------------------------------------
extern "C" void kernel_launch(void* const* d_in, const int* in_sizes, int n_in,
                              void* d_out, int out_size) {
    const float* enc  = (const float*)d_in[0];
    const float* dec  = (const float*)d_in[1];
    const void*  mask = d_in[2];
    const float* We   = (const float*)d_in[3];
    const float* Wd   = (const float*)d_in[4];
    const float* v    = (const float*)d_in[5];

    float* out_ctx  = (float*)d_out;
    float* out_attn = out_ctx + B * ENC;

    cudaFuncSetAttribute(energy_wmma_kernel,
                         cudaFuncAttributeMaxDynamicSharedMemorySize, DYN_SMEM);

    detect_mask_kernel<<<1, 256>>>((const unsigned char*)mask);
    projdec_kernel<<<B, 256>>>(dec, Wd);
    energy_wmma_kernel<<<dim3(T / TILE_M, B), 512, DYN_SMEM>>>(enc, We, v);
    softmax_kernel<<<B, 256>>>(mask, out_attn);
    context_kernel<<<dim3(ENC / 128, B), 128>>>(enc, out_attn, out_ctx);
}

// round 4
// speedup vs baseline: 3.3250x; 1.7124x over previous
#include <cuda_runtime.h>
#include <cuda_fp16.h>
#include <math.h>
#include <stdint.h>
#include <mma.h>

using namespace nvcuda;

// Problem constants
#define B    64
#define T    2048
#define ENC  512
#define DEC  512
#define ATTN 256

// Energy GEMM tiling
#define TILE_M  128
#define KC      32                 // K per pipeline chunk
#define NCHUNK  (ENC / KC)         // 16

#define A_LD_H  48                 // 32 + 16 pad (halves)
#define B_LD_H  272                // 256 + 16 pad (halves)
#define C_LD    264

#define AF_BYTES (TILE_M * KC * 4)          // 16384
#define BF_BYTES (KC * ATTN * 4)            // 32768
#define AH_OFF   (AF_BYTES + BF_BYTES)      // 49152
#define AH_BYTES (TILE_M * A_LD_H * 2)      // 12288
#define BH_OFF   (AH_OFF + AH_BYTES)        // 61440
#define BH_BYTES (KC * B_LD_H * 2)          // 17408
#define STAGE_B  (BH_OFF + BH_BYTES)        // 78848
#define META_B   2048
#define DYN_SMEM (META_B + 2 * STAGE_B)     // 159744

// ---- scratch (no allocations allowed) ----
__device__ float g_proj_dec[B * ATTN];
__device__ float g_energy[B * T];
__device__ int   g_mask_is_byte;

// ---------------------------------------------------------------------------
__device__ __forceinline__ uint32_t smem_u32(const void* p) {
    uint32_t a;
    asm("{ .reg .u64 t; cvta.to.shared.u64 t, %1; cvt.u32.u64 %0, t; }" : "=r"(a) : "l"(p));
    return a;
}
__device__ __forceinline__ float fast_tanh(float x) {
    float y; asm("tanh.approx.f32 %0, %1;" : "=f"(y) : "f"(x)); return y;
}
__device__ __forceinline__ void cp_async16(uint32_t s, const void* g) {
    asm volatile("cp.async.cg.shared.global [%0], [%1], 16;" :: "r"(s), "l"(g));
}
#define CP_COMMIT() asm volatile("cp.async.commit_group;" ::: "memory")
#define CP_WAIT1()  asm volatile("cp.async.wait_group 1;"  ::: "memory")
#define CP_WAIT0()  asm volatile("cp.async.wait_group 0;"  ::: "memory")

// ---------------------------------------------------------------------------
// mask dtype detection (byte bools vs int32 0/1)
// ---------------------------------------------------------------------------
__global__ void detect_mask_kernel(const unsigned char* __restrict__ m) {
    __shared__ int f;
    if (threadIdx.x == 0) f = 0;
    __syncthreads();
    int local = 0;
    for (int i = threadIdx.x; i < B * T; i += blockDim.x)
        if ((i & 3) && m[i]) local = 1;
    if (local) atomicOr(&f, 1);
    __syncthreads();
    if (threadIdx.x == 0) g_mask_is_byte = f;
}

// ---------------------------------------------------------------------------
// proj_dec[b,a] = dec[b,:] @ W_dec[:,a]
// ---------------------------------------------------------------------------
__global__ void projdec_kernel(const float* __restrict__ dec,
                               const float* __restrict__ Wd) {
    __shared__ float sd[DEC];
    const int b = blockIdx.x, tid = threadIdx.x;
    sd[tid]       = dec[b * DEC + tid];
    sd[tid + 256] = dec[b * DEC + tid + 256];
    __syncthreads();
    float acc = 0.f;
    #pragma unroll 8
    for (int k = 0; k < DEC; k++)
        acc = fmaf(sd[k], Wd[k * ATTN + tid], acc);
    g_proj_dec[b * ATTN + tid] = acc;
}

// ---------------------------------------------------------------------------
// Fused energy kernel: fp16 WMMA GEMM (128x256x512, f32 accum) + tanh/dot-v.
// grid (T/128, B), block 512 (16 warps, 4x4 warp grid, 32x64 warp tile).
// ---------------------------------------------------------------------------
__device__ __forceinline__ void load_chunk(const float* __restrict__ enc_tile,
                                           const float* __restrict__ We,
                                           int c, uint32_t st, int tid) {
    const int koff = c * KC;
    // A: 128 rows x 32 f32 (row stride ENC) -> dense 128B rows in staging
    #pragma unroll
    for (int it = 0; it < 2; it++) {
        int idx = it * 512 + tid;
        int row = idx >> 3, seg = idx & 7;
        cp_async16(st + (uint32_t)(row * 128 + seg * 16),
                   enc_tile + (size_t)row * ENC + koff + seg * 4);
    }
    // B: 32 contiguous rows of We (32*256 f32, fully dense) -> dense staging
    const float* bsrc = We + (size_t)koff * ATTN;
    #pragma unroll
    for (int it = 0; it < 4; it++) {
        int i = it * 512 + tid;
        cp_async16(st + AF_BYTES + (uint32_t)i * 16, bsrc + i * 4);
    }
}

__global__ void __launch_bounds__(512, 1)
energy_wmma_kernel(const float* __restrict__ enc,
                   const float* __restrict__ We,
                   const float* __restrict__ v) {
    extern __shared__ char dsm[];
    float* pd_s = (float*)dsm;                       // 256 f32
    float* v_s  = (float*)(dsm + ATTN * 4);          // 256 f32
    char*  pipe = dsm + META_B;
    float* c_s  = (float*)(dsm + META_B);            // epilogue reuse

    const uint32_t pipe_u = smem_u32(pipe);

    const int tid  = threadIdx.x;
    const int wid  = tid >> 5;
    const int wm   = wid & 3;          // 0..3  (M)
    const int wn   = wid >> 2;         // 0..3  (N)
    const int b    = blockIdx.y;
    const int t0   = blockIdx.x * TILE_M;
    const float* enc_tile = enc + ((size_t)b * T + t0) * ENC;

    if (tid < 256) {
        pd_s[tid] = g_proj_dec[b * ATTN + tid];
        v_s[tid]  = v[tid];
    }

    wmma::fragment<wmma::accumulator, 16, 16, 16, float> cf[2][4];
    #pragma unroll
    for (int i = 0; i < 2; i++)
        #pragma unroll
        for (int j = 0; j < 4; j++)
            wmma::fill_fragment(cf[i][j], 0.0f);

    // prologue: chunk 0 -> stage 0
    load_chunk(enc_tile, We, 0, pipe_u, tid);
    CP_COMMIT();

    for (int c = 0; c < NCHUNK; c++) {
        const int sp = c & 1;
        if (c + 1 < NCHUNK) {
            load_chunk(enc_tile, We, c + 1, pipe_u + (1 - sp) * STAGE_B, tid);
            CP_COMMIT();
            CP_WAIT1();
        } else {
            CP_WAIT0();
        }
        __syncthreads();                 // staging[sp] f32 resident

        // ---- convert f32 staging -> half buffers ----
        {
            const float* af = (const float*)(pipe + sp * STAGE_B);
            __half* ah = (__half*)(pipe + sp * STAGE_B + AH_OFF);
            #pragma unroll
            for (int p = 0; p < 2; p++) {                 // A: 4096 floats
                int idx = (p * 512 + tid) * 4;
                float4 x = *(const float4*)(af + idx);
                int row = idx >> 5, col = idx & 31;
                union { uint2 u; __half2 h[2]; } cv;
                cv.h[0] = __floats2half2_rn(x.x, x.y);
                cv.h[1] = __floats2half2_rn(x.z, x.w);
                *(uint2*)(ah + row * A_LD_H + col) = cv.u;
            }
            const float* bf = (const float*)(pipe + sp * STAGE_B + AF_BYTES);
            __half* bh = (__half*)(pipe + sp * STAGE_B + BH_OFF);
            #pragma unroll
            for (int p = 0; p < 4; p++) {                 // B: 8192 floats
                int idx = (p * 512 + tid) * 4;
                float4 x = *(const float4*)(bf + idx);
                int row = idx >> 8, col = idx & 255;
                union { uint2 u; __half2 h[2]; } cv;
                cv.h[0] = __floats2half2_rn(x.x, x.y);
                cv.h[1] = __floats2half2_rn(x.z, x.w);
                *(uint2*)(bh + row * B_LD_H + col) = cv.u;
            }
        }
        __syncthreads();                 // half buffers ready

        const __half* a_s = (const __half*)(pipe + sp * STAGE_B + AH_OFF);
        const __half* b_s = (const __half*)(pipe + sp * STAGE_B + BH_OFF);

        #pragma unroll
        for (int ks = 0; ks < KC / 16; ks++) {
            wmma::fragment<wmma::matrix_a, 16, 16, 16, __half, wmma::row_major> af[2];
            #pragma unroll
            for (int i = 0; i < 2; i++)
                wmma::load_matrix_sync(af[i],
                    a_s + (size_t)(wm * 32 + i * 16) * A_LD_H + ks * 16, A_LD_H);
            #pragma unroll
            for (int j = 0; j < 4; j++) {
                wmma::fragment<wmma::matrix_b, 16, 16, 16, __half, wmma::row_major> bfrag;
                wmma::load_matrix_sync(bfrag,
                    b_s + (size_t)(ks * 16) * B_LD_H + wn * 64 + j * 16, B_LD_H);
                #pragma unroll
                for (int i = 0; i < 2; i++)
                    wmma::mma_sync(cf[i][j], af[i], bfrag, cf[i][j]);
            }
        }
        __syncthreads();
    }

    // store C tile (128 x 256, ld 264) and reduce
    #pragma unroll
    for (int i = 0; i < 2; i++)
        #pragma unroll
        for (int j = 0; j < 4; j++)
            wmma::store_matrix_sync(
                c_s + (size_t)(wm * 32 + i * 16) * C_LD + wn * 64 + j * 16,
                cf[i][j], C_LD, wmma::mem_row_major);
    __syncthreads();

    const int row = tid >> 2, q = tid & 3;
    const float* crow = c_s + (size_t)row * C_LD + q * 64;
    const float* pdq  = pd_s + q * 64;
    const float* vq   = v_s + q * 64;
    float e = 0.f;
    #pragma unroll 8
    for (int j = 0; j < 64; j++)
        e = fmaf(fast_tanh(crow[j] + pdq[j]), vq[j], e);
    e += __shfl_xor_sync(0xffffffffu, e, 1);
    e += __shfl_xor_sync(0xffffffffu, e, 2);
    if (q == 0)
        g_energy[b * T + t0 + row] = e;
}

// ---------------------------------------------------------------------------
// masked softmax over T
// ---------------------------------------------------------------------------
__global__ void softmax_kernel(const void* __restrict__ mask,
                               float* __restrict__ attn_out) {
    const int b = blockIdx.x, tid = threadIdx.x;
    const bool isbyte = (g_mask_is_byte != 0);
    const unsigned char* mb = (const unsigned char*)mask;
    const int*           mi = (const int*)mask;

    float e[8];
    #pragma unroll
    for (int j = 0; j < 8; j++) {
        const int i = b * T + tid + j * 256;
        const bool m = isbyte ? (mb[i] != 0) : (mi[i] != 0);
        e[j] = m ? -INFINITY : g_energy[i];
    }

    __shared__ float sred[32];
    float mx = e[0];
    #pragma unroll
    for (int j = 1; j < 8; j++) mx = fmaxf(mx, e[j]);
    #pragma unroll
    for (int o = 16; o > 0; o >>= 1)
        mx = fmaxf(mx, __shfl_xor_sync(0xffffffffu, mx, o));
    if ((tid & 31) == 0) sred[tid >> 5] = mx;
    __syncthreads();
    if (tid < 32) {
        float v2 = (tid < 8) ? sred[tid] : -INFINITY;
        #pragma unroll
        for (int o = 4; o > 0; o >>= 1)
            v2 = fmaxf(v2, __shfl_xor_sync(0xffffffffu, v2, o));
        if (tid == 0) sred[0] = v2;
    }
    __syncthreads();
    mx = sred[0];
    __syncthreads();

    const bool allmasked = !(mx > -INFINITY);

    float ex[8], s = 0.f;
    #pragma unroll
    for (int j = 0; j < 8; j++) {
        ex[j] = (allmasked || e[j] == -INFINITY) ? 0.f : expf(e[j] - mx);
        s += ex[j];
    }
    #pragma unroll
    for (int o = 16; o > 0; o >>= 1)
        s += __shfl_xor_sync(0xffffffffu, s, o);
    if ((tid & 31) == 0) sred[tid >> 5] = s;
    __syncthreads();
    if (tid < 32) {
        float v2 = (tid < 8) ? sred[tid] : 0.f;
        #pragma unroll
        for (int o = 4; o > 0; o >>= 1)
            v2 += __shfl_xor_sync(0xffffffffu, v2, o);
        if (tid == 0) sred[0] = v2;
    }
    __syncthreads();
    s = sred[0];

    const float inv = (s > 0.f) ? (1.f / s) : 0.f;
    #pragma unroll
    for (int j = 0; j < 8; j++)
        attn_out[b * T + tid + j * 256] = ex[j] * inv;
}

// ---------------------------------------------------------------------------
// context[b,e] = sum_t attn_w[b,t] * enc[b,t,e]
// ---------------------------------------------------------------------------
__global__ void context_kernel(const float* __restrict__ enc,
                               const float* __restrict__ attn,
                               float* __restrict__ ctx) {
    __shared__ float sw[T];
    const int b = blockIdx.y;
    const int e = blockIdx.x * 128 + threadIdx.x;

    for (int i = threadIdx.x; i < T; i += 128)
        sw[i] = attn[b * T + i];
    __syncthreads();

    const float* ep = enc + (size_t)b * T * ENC + e;
    float a0 = 0.f, a1 = 0.f, a2 = 0.f, a3 = 0.f;
    for (int t = 0; t < T; t += 4) {
        a0 = fmaf(sw[t + 0], ep[(size_t)(t + 0) * ENC], a0);
        a1 = fmaf(sw[t + 1], ep[(size_t)(t + 1) * ENC], a1);
        a2 = fmaf(sw[t + 2], ep[(size_t)(t + 2) * ENC], a2);
        a3 = fmaf(sw[t + 3], ep[(size_t)(t + 3) * ENC], a3);
    }
    ctx[b * ENC + e] = (a0 + a1) + (a2 + a3);
}

// ---------------------------------------------------------------------------
extern "C" void kernel_launch(void* const* d_in, const int* in_sizes, int n_in,
                              void* d_out, int out_size) {
    const float* enc  = (const float*)d_in[0];
    const float* dec  = (const float*)d_in[1];
    const void*  mask = d_in[2];
    const float* We   = (const float*)d_in[3];
    const float* Wd   = (const float*)d_in[4];
    const float* v    = (const float*)d_in[5];

    float* out_ctx  = (float*)d_out;
    float* out_attn = out_ctx + B * ENC;

    cudaFuncSetAttribute(energy_wmma_kernel,
                         cudaFuncAttributeMaxDynamicSharedMemorySize, DYN_SMEM);

    detect_mask_kernel<<<1, 1024>>>((const unsigned char*)mask);
    projdec_kernel<<<B, 256>>>(dec, Wd);
    energy_wmma_kernel<<<dim3(T / TILE_M, B), 512, DYN_SMEM>>>(enc, We, v);
    softmax_kernel<<<B, 256>>>(mask, out_attn);
    context_kernel<<<dim3(ENC / 128, B), 128>>>(enc, out_attn, out_ctx);
}

// round 5
// speedup vs baseline: 3.7661x; 1.1327x over previous
#include <cuda_runtime.h>
#include <cuda_fp16.h>
#include <math.h>
#include <stdint.h>
#include <mma.h>

using namespace nvcuda;

// Problem constants
#define B    64
#define T    2048
#define ENC  512
#define DEC  512
#define ATTN 256

// Energy GEMM tiling (all-half pipeline)
#define TILE_M  128
#define KC      64                 // K per pipeline chunk (half)
#define NCHUNK  (ENC / KC)         // 8

#define A_LD_H  72                 // 64 + 8 pad (halves)
#define B_LD_H  264                // 256 + 8 pad (halves)
#define C_LD    264

#define A_BYTES (TILE_M * A_LD_H * 2)       // 18432
#define B_BYTES (KC * B_LD_H * 2)           // 33792
#define STAGE_B (A_BYTES + B_BYTES)         // 52224
#define META_B  2048
#define DYN_SMEM (META_B + TILE_M * C_LD * 4)   // 2048 + 135168 = 137216

// ---- scratch (no allocations allowed) ----
__device__ __half g_enc_h[(size_t)B * T * ENC];   // 128 MB
__device__ __half g_We_h[ENC * ATTN];
__device__ float  g_proj_dec[B * ATTN];
__device__ float  g_energy[B * T];
__device__ int    g_mask_is_byte;

// ---------------------------------------------------------------------------
__device__ __forceinline__ uint32_t smem_u32(const void* p) {
    uint32_t a;
    asm("{ .reg .u64 t; cvta.to.shared.u64 t, %1; cvt.u32.u64 %0, t; }" : "=r"(a) : "l"(p));
    return a;
}
__device__ __forceinline__ float fast_tanh(float x) {
    float y; asm("tanh.approx.f32 %0, %1;" : "=f"(y) : "f"(x)); return y;
}
__device__ __forceinline__ void cp_async16(uint32_t s, const void* g) {
    asm volatile("cp.async.cg.shared.global [%0], [%1], 16;" :: "r"(s), "l"(g));
}
#define CP_COMMIT() asm volatile("cp.async.commit_group;" ::: "memory")
#define CP_WAIT1()  asm volatile("cp.async.wait_group 1;"  ::: "memory")
#define CP_WAIT0()  asm volatile("cp.async.wait_group 0;"  ::: "memory")

// ---------------------------------------------------------------------------
// mask dtype detection (byte bools vs int32 0/1)
// ---------------------------------------------------------------------------
__global__ void detect_mask_kernel(const unsigned char* __restrict__ m) {
    __shared__ int f;
    if (threadIdx.x == 0) f = 0;
    __syncthreads();
    int local = 0;
    for (int i = threadIdx.x; i < B * T; i += blockDim.x)
        if ((i & 3) && m[i]) local = 1;
    if (local) atomicOr(&f, 1);
    __syncthreads();
    if (threadIdx.x == 0) g_mask_is_byte = f;
}

// ---------------------------------------------------------------------------
// f32 -> half conversion: enc (67.1M elems), grid-strided float4 -> 4 halves
// ---------------------------------------------------------------------------
__global__ void __launch_bounds__(512)
convert_enc_kernel(const float* __restrict__ enc) {
    const size_t n4 = (size_t)B * T * ENC / 4;
    const float4* in = (const float4*)enc;
    uint2* out = (uint2*)g_enc_h;
    for (size_t i = (size_t)blockIdx.x * blockDim.x + threadIdx.x;
         i < n4; i += (size_t)gridDim.x * blockDim.x) {
        float4 x = in[i];
        union { uint2 u; __half2 h[2]; } cv;
        cv.h[0] = __floats2half2_rn(x.x, x.y);
        cv.h[1] = __floats2half2_rn(x.z, x.w);
        out[i] = cv.u;
    }
}

__global__ void __launch_bounds__(512)
convert_we_kernel(const float* __restrict__ We) {
    const int n4 = ENC * ATTN / 4;
    const float4* in = (const float4*)We;
    uint2* out = (uint2*)g_We_h;
    for (int i = blockIdx.x * blockDim.x + threadIdx.x; i < n4;
         i += gridDim.x * blockDim.x) {
        float4 x = in[i];
        union { uint2 u; __half2 h[2]; } cv;
        cv.h[0] = __floats2half2_rn(x.x, x.y);
        cv.h[1] = __floats2half2_rn(x.z, x.w);
        out[i] = cv.u;
    }
}

// ---------------------------------------------------------------------------
// proj_dec[b,a] = dec[b,:] @ W_dec[:,a]   (fp32, tiny)
// ---------------------------------------------------------------------------
__global__ void projdec_kernel(const float* __restrict__ dec,
                               const float* __restrict__ Wd) {
    __shared__ float sd[DEC];
    const int b = blockIdx.x, tid = threadIdx.x;
    sd[tid]       = dec[b * DEC + tid];
    sd[tid + 256] = dec[b * DEC + tid + 256];
    __syncthreads();
    float acc = 0.f;
    #pragma unroll 8
    for (int k = 0; k < DEC; k++)
        acc = fmaf(sd[k], Wd[k * ATTN + tid], acc);
    g_proj_dec[b * ATTN + tid] = acc;
}

// ---------------------------------------------------------------------------
// Fused energy kernel: pure fp16 WMMA GEMM (128x256x512, f32 accum) + epilogue
// grid (T/128, B), block 512 (16 warps, 4x4 warp grid, 32x64 warp tile).
// ---------------------------------------------------------------------------
__device__ __forceinline__ void load_chunk(const __half* __restrict__ enc_tile,
                                           int c, uint32_t st, int tid) {
    const int koff = c * KC;
    // A: 128 rows x 64 halves (128B dense per row, row stride ENC halves)
    #pragma unroll
    for (int it = 0; it < 2; it++) {
        int idx = it * 512 + tid;
        int row = idx >> 3, seg = idx & 7;          // 8 x 16B per row
        cp_async16(st + (uint32_t)(row * A_LD_H + seg * 8) * 2,
                   enc_tile + (size_t)row * ENC + koff + seg * 8);
    }
    // B: 64 rows x 256 halves (512B dense rows from g_We_h)
    const __half* bsrc = g_We_h + (size_t)koff * ATTN;
    #pragma unroll
    for (int it = 0; it < 4; it++) {
        int idx = it * 512 + tid;
        int row = idx >> 5, seg = idx & 31;         // 32 x 16B per row
        cp_async16(st + A_BYTES + (uint32_t)(row * B_LD_H + seg * 8) * 2,
                   bsrc + (size_t)row * ATTN + seg * 8);
    }
}

__global__ void __launch_bounds__(512, 1)
energy_wmma_kernel(const float* __restrict__ v) {
    extern __shared__ char dsm[];
    float* pd_s = (float*)dsm;                       // 256 f32
    float* v_s  = (float*)(dsm + ATTN * 4);          // 256 f32
    char*  pipe = dsm + META_B;
    float* c_s  = (float*)(dsm + META_B);            // epilogue reuse

    const uint32_t pipe_u = smem_u32(pipe);

    const int tid  = threadIdx.x;
    const int wid  = tid >> 5;
    const int wm   = wid & 3;          // 0..3  (M)
    const int wn   = wid >> 2;         // 0..3  (N)
    const int b    = blockIdx.y;
    const int t0   = blockIdx.x * TILE_M;
    const __half* enc_tile = g_enc_h + ((size_t)b * T + t0) * ENC;

    if (tid < 256) {
        pd_s[tid] = g_proj_dec[b * ATTN + tid];
        v_s[tid]  = v[tid];
    }

    wmma::fragment<wmma::accumulator, 16, 16, 16, float> cf[2][4];
    #pragma unroll
    for (int i = 0; i < 2; i++)
        #pragma unroll
        for (int j = 0; j < 4; j++)
            wmma::fill_fragment(cf[i][j], 0.0f);

    load_chunk(enc_tile, 0, pipe_u, tid);
    CP_COMMIT();

    for (int c = 0; c < NCHUNK; c++) {
        const int sp = c & 1;
        if (c + 1 < NCHUNK) {
            load_chunk(enc_tile, c + 1, pipe_u + (1 - sp) * STAGE_B, tid);
            CP_COMMIT();
            CP_WAIT1();
        } else {
            CP_WAIT0();
        }
        __syncthreads();

        const __half* a_s = (const __half*)(pipe + sp * STAGE_B);
        const __half* b_s = (const __half*)(pipe + sp * STAGE_B + A_BYTES);

        #pragma unroll
        for (int ks = 0; ks < KC / 16; ks++) {
            wmma::fragment<wmma::matrix_a, 16, 16, 16, __half, wmma::row_major> af[2];
            #pragma unroll
            for (int i = 0; i < 2; i++)
                wmma::load_matrix_sync(af[i],
                    a_s + (size_t)(wm * 32 + i * 16) * A_LD_H + ks * 16, A_LD_H);
            #pragma unroll
            for (int j = 0; j < 4; j++) {
                wmma::fragment<wmma::matrix_b, 16, 16, 16, __half, wmma::row_major> bfrag;
                wmma::load_matrix_sync(bfrag,
                    b_s + (size_t)(ks * 16) * B_LD_H + wn * 64 + j * 16, B_LD_H);
                #pragma unroll
                for (int i = 0; i < 2; i++)
                    wmma::mma_sync(cf[i][j], af[i], bfrag, cf[i][j]);
            }
        }
        __syncthreads();
    }

    // store C tile (128 x 256, ld 264) and reduce
    #pragma unroll
    for (int i = 0; i < 2; i++)
        #pragma unroll
        for (int j = 0; j < 4; j++)
            wmma::store_matrix_sync(
                c_s + (size_t)(wm * 32 + i * 16) * C_LD + wn * 64 + j * 16,
                cf[i][j], C_LD, wmma::mem_row_major);
    __syncthreads();

    const int row = tid >> 2, q = tid & 3;
    const float* crow = c_s + (size_t)row * C_LD + q * 64;
    const float* pdq  = pd_s + q * 64;
    const float* vq   = v_s + q * 64;
    float e = 0.f;
    #pragma unroll 8
    for (int j = 0; j < 64; j++)
        e = fmaf(fast_tanh(crow[j] + pdq[j]), vq[j], e);
    e += __shfl_xor_sync(0xffffffffu, e, 1);
    e += __shfl_xor_sync(0xffffffffu, e, 2);
    if (q == 0)
        g_energy[b * T + t0 + row] = e;
}

// ---------------------------------------------------------------------------
// masked softmax over T
// ---------------------------------------------------------------------------
__global__ void softmax_kernel(const void* __restrict__ mask,
                               float* __restrict__ attn_out) {
    const int b = blockIdx.x, tid = threadIdx.x;
    const bool isbyte = (g_mask_is_byte != 0);
    const unsigned char* mb = (const unsigned char*)mask;
    const int*           mi = (const int*)mask;

    float e[8];
    #pragma unroll
    for (int j = 0; j < 8; j++) {
        const int i = b * T + tid + j * 256;
        const bool m = isbyte ? (mb[i] != 0) : (mi[i] != 0);
        e[j] = m ? -INFINITY : g_energy[i];
    }

    __shared__ float sred[32];
    float mx = e[0];
    #pragma unroll
    for (int j = 1; j < 8; j++) mx = fmaxf(mx, e[j]);
    #pragma unroll
    for (int o = 16; o > 0; o >>= 1)
        mx = fmaxf(mx, __shfl_xor_sync(0xffffffffu, mx, o));
    if ((tid & 31) == 0) sred[tid >> 5] = mx;
    __syncthreads();
    if (tid < 32) {
        float v2 = (tid < 8) ? sred[tid] : -INFINITY;
        #pragma unroll
        for (int o = 4; o > 0; o >>= 1)
            v2 = fmaxf(v2, __shfl_xor_sync(0xffffffffu, v2, o));
        if (tid == 0) sred[0] = v2;
    }
    __syncthreads();
    mx = sred[0];
    __syncthreads();

    const bool allmasked = !(mx > -INFINITY);

    float ex[8], s = 0.f;
    #pragma unroll
    for (int j = 0; j < 8; j++) {
        ex[j] = (allmasked || e[j] == -INFINITY) ? 0.f : expf(e[j] - mx);
        s += ex[j];
    }
    #pragma unroll
    for (int o = 16; o > 0; o >>= 1)
        s += __shfl_xor_sync(0xffffffffu, s, o);
    if ((tid & 31) == 0) sred[tid >> 5] = s;
    __syncthreads();
    if (tid < 32) {
        float v2 = (tid < 8) ? sred[tid] : 0.f;
        #pragma unroll
        for (int o = 4; o > 0; o >>= 1)
            v2 += __shfl_xor_sync(0xffffffffu, v2, o);
        if (tid == 0) sred[0] = v2;
    }
    __syncthreads();
    s = sred[0];

    const float inv = (s > 0.f) ? (1.f / s) : 0.f;
    #pragma unroll
    for (int j = 0; j < 8; j++)
        attn_out[b * T + tid + j * 256] = ex[j] * inv;
}

// ---------------------------------------------------------------------------
// context[b,e] = sum_t attn_w[b,t] * enc_h[b,t,e]  (half enc, f32 accum)
// ---------------------------------------------------------------------------
__global__ void context_kernel(const float* __restrict__ attn,
                               float* __restrict__ ctx) {
    __shared__ float sw[T];
    const int b = blockIdx.y;
    const int e = blockIdx.x * 128 + threadIdx.x;

    for (int i = threadIdx.x; i < T; i += 128)
        sw[i] = attn[b * T + i];
    __syncthreads();

    const __half* ep = g_enc_h + (size_t)b * T * ENC + e;
    float a0 = 0.f, a1 = 0.f, a2 = 0.f, a3 = 0.f;
    for (int t = 0; t < T; t += 4) {
        a0 = fmaf(sw[t + 0], __half2float(ep[(size_t)(t + 0) * ENC]), a0);
        a1 = fmaf(sw[t + 1], __half2float(ep[(size_t)(t + 1) * ENC]), a1);
        a2 = fmaf(sw[t + 2], __half2float(ep[(size_t)(t + 2) * ENC]), a2);
        a3 = fmaf(sw[t + 3], __half2float(ep[(size_t)(t + 3) * ENC]), a3);
    }
    ctx[b * ENC + e] = (a0 + a1) + (a2 + a3);
}

// ---------------------------------------------------------------------------
extern "C" void kernel_launch(void* const* d_in, const int* in_sizes, int n_in,
                              void* d_out, int out_size) {
    const float* enc  = (const float*)d_in[0];
    const float* dec  = (const float*)d_in[1];
    const void*  mask = d_in[2];
    const float* We   = (const float*)d_in[3];
    const float* Wd   = (const float*)d_in[4];
    const float* v    = (const float*)d_in[5];

    float* out_ctx  = (float*)d_out;
    float* out_attn = out_ctx + B * ENC;

    cudaFuncSetAttribute(energy_wmma_kernel,
                         cudaFuncAttributeMaxDynamicSharedMemorySize, DYN_SMEM);

    detect_mask_kernel<<<1, 1024>>>((const unsigned char*)mask);
    convert_enc_kernel<<<2048, 512>>>(enc);
    convert_we_kernel<<<64, 512>>>(We);
    projdec_kernel<<<B, 256>>>(dec, Wd);
    energy_wmma_kernel<<<dim3(T / TILE_M, B), 512, DYN_SMEM>>>(v);
    softmax_kernel<<<B, 256>>>(mask, out_attn);
    context_kernel<<<dim3(ENC / 128, B), 128>>>(out_attn, out_ctx);
}

// round 6
// speedup vs baseline: 4.1818x; 1.1104x over previous
#include <cuda_runtime.h>
#include <cuda_fp16.h>
#include <math.h>
#include <stdint.h>
#include <mma.h>

using namespace nvcuda;

// Problem constants
#define B    64
#define T    2048
#define ENC  512
#define DEC  512
#define ATTN 256

// Energy GEMM tiling (all-half pipeline)
#define TILE_M  128
#define KC      64                 // K per pipeline chunk (half)
#define NCHUNK  (ENC / KC)         // 8
#define STAGES  3

#define A_LD_H  72                 // 64 + 8 pad (halves)
#define B_LD_H  264                // 256 + 8 pad (halves)
#define C_LD    264

#define A_BYTES (TILE_M * A_LD_H * 2)       // 18432
#define B_BYTES (KC * B_LD_H * 2)           // 33792
#define STAGE_B (A_BYTES + B_BYTES)         // 52224
#define META_B  2048
#define DYN_SMEM (META_B + STAGES * STAGE_B)   // 158720 (>= META_B + C tile 135168)

// ---- scratch (no allocations allowed) ----
__device__ __half g_enc_h[(size_t)B * T * ENC];   // 128 MB
__device__ __half g_We_h[ENC * ATTN];
__device__ float  g_proj_dec[B * ATTN];
__device__ float  g_energy[B * T];
__device__ int    g_mask_is_byte;

// ---------------------------------------------------------------------------
__device__ __forceinline__ uint32_t smem_u32(const void* p) {
    uint32_t a;
    asm("{ .reg .u64 t; cvta.to.shared.u64 t, %1; cvt.u32.u64 %0, t; }" : "=r"(a) : "l"(p));
    return a;
}
__device__ __forceinline__ float fast_tanh(float x) {
    float y; asm("tanh.approx.f32 %0, %1;" : "=f"(y) : "f"(x)); return y;
}
__device__ __forceinline__ void cp_async16(uint32_t s, const void* g) {
    asm volatile("cp.async.cg.shared.global [%0], [%1], 16;" :: "r"(s), "l"(g));
}
#define CP_COMMIT() asm volatile("cp.async.commit_group;" ::: "memory")
#define CP_WAIT(n)  asm volatile("cp.async.wait_group %0;" :: "n"(n) : "memory")

// ---------------------------------------------------------------------------
// f32 -> half conversion: enc (67.1M elems), grid-strided float4 -> 4 halves
// ---------------------------------------------------------------------------
__global__ void __launch_bounds__(512)
convert_enc_kernel(const float* __restrict__ enc) {
    const size_t n4 = (size_t)B * T * ENC / 4;
    const float4* in = (const float4*)enc;
    uint2* out = (uint2*)g_enc_h;
    for (size_t i = (size_t)blockIdx.x * blockDim.x + threadIdx.x;
         i < n4; i += (size_t)gridDim.x * blockDim.x) {
        float4 x = in[i];
        union { uint2 u; __half2 h[2]; } cv;
        cv.h[0] = __floats2half2_rn(x.x, x.y);
        cv.h[1] = __floats2half2_rn(x.z, x.w);
        out[i] = cv.u;
    }
}

// ---------------------------------------------------------------------------
// Fused prologue: projdec (blocks 0-255, split-K), convert_we (256-287),
// mask detection (288). 256 threads per block.
// ---------------------------------------------------------------------------
__global__ void __launch_bounds__(256)
prep_kernel(const float* __restrict__ dec, const float* __restrict__ Wd,
            const float* __restrict__ We, const unsigned char* __restrict__ mask) {
    const int blk = blockIdx.x, tid = threadIdx.x;

    if (blk < 256) {
        // ---- projdec split-K: block = (b, quarter of A); 4-way K split ----
        __shared__ float sd[DEC];
        __shared__ float sp[256];
        const int b = blk >> 2, q = blk & 3;
        const int a = q * 64 + (tid & 63);
        const int kseg = tid >> 6;                 // 0..3 -> K range [kseg*128, +128)
        sd[tid]       = dec[b * DEC + tid];
        sd[tid + 256] = dec[b * DEC + tid + 256];
        __syncthreads();
        const float* wp = Wd + (size_t)(kseg * 128) * ATTN + a;
        const float* dp = sd + kseg * 128;
        float a0 = 0.f, a1 = 0.f, a2 = 0.f, a3 = 0.f;
        #pragma unroll 8
        for (int i = 0; i < 128; i += 4) {
            a0 = fmaf(dp[i + 0], wp[(size_t)(i + 0) * ATTN], a0);
            a1 = fmaf(dp[i + 1], wp[(size_t)(i + 1) * ATTN], a1);
            a2 = fmaf(dp[i + 2], wp[(size_t)(i + 2) * ATTN], a2);
            a3 = fmaf(dp[i + 3], wp[(size_t)(i + 3) * ATTN], a3);
        }
        sp[tid] = (a0 + a1) + (a2 + a3);
        __syncthreads();
        if (tid < 64)
            g_proj_dec[b * ATTN + q * 64 + tid] =
                sp[tid] + sp[tid + 64] + sp[tid + 128] + sp[tid + 192];
    } else if (blk < 288) {
        // ---- convert W_enc f32 -> half (131072 elems = 32768 float4) ----
        const int blk2 = blk - 256;
        const float4* in = (const float4*)We;
        uint2* out = (uint2*)g_We_h;
        #pragma unroll
        for (int j = 0; j < 4; j++) {
            int i = blk2 * 256 + tid + j * 8192;
            float4 x = in[i];
            union { uint2 u; __half2 h[2]; } cv;
            cv.h[0] = __floats2half2_rn(x.x, x.y);
            cv.h[1] = __floats2half2_rn(x.z, x.w);
            out[i] = cv.u;
        }
    } else {
        // ---- mask dtype detect: any nonzero byte outside byte-0 of words ----
        __shared__ int f;
        if (tid == 0) f = 0;
        __syncthreads();
        const uint4* m4 = (const uint4*)mask;      // 8192 uint4 total
        uint32_t acc = 0;
        #pragma unroll 8
        for (int j = 0; j < 32; j++) {
            uint4 w = m4[tid + j * 256];
            acc |= (w.x | w.y | w.z | w.w) & 0xFFFFFF00u;
        }
        if (acc) atomicOr(&f, 1);
        __syncthreads();
        if (tid == 0) g_mask_is_byte = f;
    }
}

// ---------------------------------------------------------------------------
// Fused energy kernel: pure fp16 WMMA GEMM (128x256x512, f32 accum) + epilogue
// grid (T/128, B), block 512 (16 warps, 4x4 warp grid, 32x64 warp tile).
// 3-stage cp.async pipeline.
// ---------------------------------------------------------------------------
__device__ __forceinline__ void load_chunk(const __half* __restrict__ enc_tile,
                                           int c, uint32_t st, int tid) {
    const int koff = c * KC;
    // A: 128 rows x 64 halves (128B dense per row, row stride ENC halves)
    #pragma unroll
    for (int it = 0; it < 2; it++) {
        int idx = it * 512 + tid;
        int row = idx >> 3, seg = idx & 7;          // 8 x 16B per row
        cp_async16(st + (uint32_t)(row * A_LD_H + seg * 8) * 2,
                   enc_tile + (size_t)row * ENC + koff + seg * 8);
    }
    // B: 64 rows x 256 halves (512B dense rows from g_We_h)
    const __half* bsrc = g_We_h + (size_t)koff * ATTN;
    #pragma unroll
    for (int it = 0; it < 4; it++) {
        int idx = it * 512 + tid;
        int row = idx >> 5, seg = idx & 31;         // 32 x 16B per row
        cp_async16(st + A_BYTES + (uint32_t)(row * B_LD_H + seg * 8) * 2,
                   bsrc + (size_t)row * ATTN + seg * 8);
    }
}

__global__ void __launch_bounds__(512, 1)
energy_wmma_kernel(const float* __restrict__ v) {
    extern __shared__ char dsm[];
    float* pd_s = (float*)dsm;                       // 256 f32
    float* v_s  = (float*)(dsm + ATTN * 4);          // 256 f32
    char*  pipe = dsm + META_B;
    float* c_s  = (float*)(dsm + META_B);            // epilogue reuse

    const uint32_t pipe_u = smem_u32(pipe);

    const int tid  = threadIdx.x;
    const int wid  = tid >> 5;
    const int wm   = wid & 3;          // 0..3  (M)
    const int wn   = wid >> 2;         // 0..3  (N)
    const int b    = blockIdx.y;
    const int t0   = blockIdx.x * TILE_M;
    const __half* enc_tile = g_enc_h + ((size_t)b * T + t0) * ENC;

    if (tid < 256) {
        pd_s[tid] = g_proj_dec[b * ATTN + tid];
        v_s[tid]  = v[tid];
    }

    wmma::fragment<wmma::accumulator, 16, 16, 16, float> cf[2][4];
    #pragma unroll
    for (int i = 0; i < 2; i++)
        #pragma unroll
        for (int j = 0; j < 4; j++)
            wmma::fill_fragment(cf[i][j], 0.0f);

    load_chunk(enc_tile, 0, pipe_u, tid);
    CP_COMMIT();
    load_chunk(enc_tile, 1, pipe_u + STAGE_B, tid);
    CP_COMMIT();

    #pragma unroll 1
    for (int c = 0; c < NCHUNK; c++) {
        const int sp = c % STAGES;
        if (c + 2 < NCHUNK) {
            load_chunk(enc_tile, c + 2, pipe_u + ((c + 2) % STAGES) * STAGE_B, tid);
            CP_COMMIT();
            CP_WAIT(2);
        } else if (c + 1 < NCHUNK) {
            CP_WAIT(1);
        } else {
            CP_WAIT(0);
        }
        __syncthreads();

        const __half* a_s = (const __half*)(pipe + sp * STAGE_B);
        const __half* b_s = (const __half*)(pipe + sp * STAGE_B + A_BYTES);

        #pragma unroll
        for (int ks = 0; ks < KC / 16; ks++) {
            wmma::fragment<wmma::matrix_a, 16, 16, 16, __half, wmma::row_major> af[2];
            #pragma unroll
            for (int i = 0; i < 2; i++)
                wmma::load_matrix_sync(af[i],
                    a_s + (size_t)(wm * 32 + i * 16) * A_LD_H + ks * 16, A_LD_H);
            #pragma unroll
            for (int j = 0; j < 4; j++) {
                wmma::fragment<wmma::matrix_b, 16, 16, 16, __half, wmma::row_major> bfrag;
                wmma::load_matrix_sync(bfrag,
                    b_s + (size_t)(ks * 16) * B_LD_H + wn * 64 + j * 16, B_LD_H);
                #pragma unroll
                for (int i = 0; i < 2; i++)
                    wmma::mma_sync(cf[i][j], af[i], bfrag, cf[i][j]);
            }
        }
        __syncthreads();
    }

    // store C tile (128 x 256, ld 264) and reduce
    #pragma unroll
    for (int i = 0; i < 2; i++)
        #pragma unroll
        for (int j = 0; j < 4; j++)
            wmma::store_matrix_sync(
                c_s + (size_t)(wm * 32 + i * 16) * C_LD + wn * 64 + j * 16,
                cf[i][j], C_LD, wmma::mem_row_major);
    __syncthreads();

    const int row = tid >> 2, q = tid & 3;
    const float* crow = c_s + (size_t)row * C_LD + q * 64;
    const float* pdq  = pd_s + q * 64;
    const float* vq   = v_s + q * 64;
    float e = 0.f;
    #pragma unroll 8
    for (int j = 0; j < 64; j++)
        e = fmaf(fast_tanh(crow[j] + pdq[j]), vq[j], e);
    e += __shfl_xor_sync(0xffffffffu, e, 1);
    e += __shfl_xor_sync(0xffffffffu, e, 2);
    if (q == 0)
        g_energy[b * T + t0 + row] = e;
}

// ---------------------------------------------------------------------------
// masked softmax over T
// ---------------------------------------------------------------------------
__global__ void softmax_kernel(const void* __restrict__ mask,
                               float* __restrict__ attn_out) {
    const int b = blockIdx.x, tid = threadIdx.x;
    const bool isbyte = (g_mask_is_byte != 0);
    const unsigned char* mb = (const unsigned char*)mask;
    const int*           mi = (const int*)mask;

    float e[8];
    #pragma unroll
    for (int j = 0; j < 8; j++) {
        const int i = b * T + tid + j * 256;
        const bool m = isbyte ? (mb[i] != 0) : (mi[i] != 0);
        e[j] = m ? -INFINITY : g_energy[i];
    }

    __shared__ float sred[32];
    float mx = e[0];
    #pragma unroll
    for (int j = 1; j < 8; j++) mx = fmaxf(mx, e[j]);
    #pragma unroll
    for (int o = 16; o > 0; o >>= 1)
        mx = fmaxf(mx, __shfl_xor_sync(0xffffffffu, mx, o));
    if ((tid & 31) == 0) sred[tid >> 5] = mx;
    __syncthreads();
    if (tid < 32) {
        float v2 = (tid < 8) ? sred[tid] : -INFINITY;
        #pragma unroll
        for (int o = 4; o > 0; o >>= 1)
            v2 = fmaxf(v2, __shfl_xor_sync(0xffffffffu, v2, o));
        if (tid == 0) sred[0] = v2;
    }
    __syncthreads();
    mx = sred[0];
    __syncthreads();

    const bool allmasked = !(mx > -INFINITY);

    float ex[8], s = 0.f;
    #pragma unroll
    for (int j = 0; j < 8; j++) {
        ex[j] = (allmasked || e[j] == -INFINITY) ? 0.f : expf(e[j] - mx);
        s += ex[j];
    }
    #pragma unroll
    for (int o = 16; o > 0; o >>= 1)
        s += __shfl_xor_sync(0xffffffffu, s, o);
    if ((tid & 31) == 0) sred[tid >> 5] = s;
    __syncthreads();
    if (tid < 32) {
        float v2 = (tid < 8) ? sred[tid] : 0.f;
        #pragma unroll
        for (int o = 4; o > 0; o >>= 1)
            v2 += __shfl_xor_sync(0xffffffffu, v2, o);
        if (tid == 0) sred[0] = v2;
    }
    __syncthreads();
    s = sred[0];

    const float inv = (s > 0.f) ? (1.f / s) : 0.f;
    #pragma unroll
    for (int j = 0; j < 8; j++)
        attn_out[b * T + tid + j * 256] = ex[j] * inv;
}

// ---------------------------------------------------------------------------
// context[b,e] = sum_t attn_w[b,t] * enc_h[b,t,e]  (half enc, f32 accum)
// ---------------------------------------------------------------------------
__global__ void context_kernel(const float* __restrict__ attn,
                               float* __restrict__ ctx) {
    __shared__ float sw[T];
    const int b = blockIdx.y;
    const int e = blockIdx.x * 128 + threadIdx.x;

    for (int i = threadIdx.x; i < T; i += 128)
        sw[i] = attn[b * T + i];
    __syncthreads();

    const __half* ep = g_enc_h + (size_t)b * T * ENC + e;
    float a0 = 0.f, a1 = 0.f, a2 = 0.f, a3 = 0.f;
    for (int t = 0; t < T; t += 4) {
        a0 = fmaf(sw[t + 0], __half2float(ep[(size_t)(t + 0) * ENC]), a0);
        a1 = fmaf(sw[t + 1], __half2float(ep[(size_t)(t + 1) * ENC]), a1);
        a2 = fmaf(sw[t + 2], __half2float(ep[(size_t)(t + 2) * ENC]), a2);
        a3 = fmaf(sw[t + 3], __half2float(ep[(size_t)(t + 3) * ENC]), a3);
    }
    ctx[b * ENC + e] = (a0 + a1) + (a2 + a3);
}

// ---------------------------------------------------------------------------
extern "C" void kernel_launch(void* const* d_in, const int* in_sizes, int n_in,
                              void* d_out, int out_size) {
    const float* enc  = (const float*)d_in[0];
    const float* dec  = (const float*)d_in[1];
    const void*  mask = d_in[2];
    const float* We   = (const float*)d_in[3];
    const float* Wd   = (const float*)d_in[4];
    const float* v    = (const float*)d_in[5];

    float* out_ctx  = (float*)d_out;
    float* out_attn = out_ctx + B * ENC;

    cudaFuncSetAttribute(energy_wmma_kernel,
                         cudaFuncAttributeMaxDynamicSharedMemorySize, DYN_SMEM);

    convert_enc_kernel<<<2048, 512>>>(enc);
    prep_kernel<<<289, 256>>>(dec, Wd, We, (const unsigned char*)mask);
    energy_wmma_kernel<<<dim3(T / TILE_M, B), 512, DYN_SMEM>>>(v);
    softmax_kernel<<<B, 256>>>(mask, out_attn);
    context_kernel<<<dim3(ENC / 128, B), 128>>>(out_attn, out_ctx);
}